// round 6
// baseline (speedup 1.0000x reference)
#include <cuda_runtime.h>
#include <math_constants.h>

// Problem constants
#define B_    16
#define D_    256
#define T_    4096
#define NQ_   8
#define BINS_ 1024
#define N_    (B_ * T_)              // 65536 vectors

#define QUANT_ELEMS (B_ * D_ * T_)   // 16,777,216
#define CODES_ELEMS (NQ_ * N_)       // 524,288

// Scratch (device globals; allocation is forbidden)
__device__ float g_resid[(size_t)N_ * D_];     // 64 MB
__device__ int   g_codes[NQ_ * N_];            // 2 MB
__device__ float g_cnorm[NQ_ * BINS_];         // 32 KB
__device__ float g_loss;

// ---------------------------------------------------------------------------
__global__ void zero_loss_kernel() { g_loss = 0.0f; }

// ---------------------------------------------------------------------------
// codebook squared norms: one warp per (q, bin) row
__global__ void cnorm_kernel(const float* __restrict__ cb) {
    int row  = blockIdx.x * 8 + (threadIdx.x >> 5);   // 0 .. NQ*BINS-1
    int lane = threadIdx.x & 31;
    const float4* c4 = (const float4*)(cb + (size_t)row * D_);
    float s = 0.0f;
    #pragma unroll
    for (int i = lane; i < D_ / 4; i += 32) {
        float4 v = c4[i];
        s += v.x * v.x + v.y * v.y + v.z * v.z + v.w * v.w;
    }
    #pragma unroll
    for (int o = 16; o > 0; o >>= 1) s += __shfl_xor_sync(0xFFFFFFFFu, s, o);
    if (lane == 0) g_cnorm[row] = s;
}

// ---------------------------------------------------------------------------
// transpose x [B][D][T] -> residual [B*T][D]
__global__ void transpose_in_kernel(const float* __restrict__ x) {
    __shared__ float tile[32][33];
    int b  = blockIdx.z;
    int d0 = blockIdx.y * 32;
    int t0 = blockIdx.x * 32;
    int tx = threadIdx.x;
    int ty = threadIdx.y;
    #pragma unroll
    for (int i = ty; i < 32; i += 8)
        tile[i][tx] = x[(size_t)b * D_ * T_ + (size_t)(d0 + i) * T_ + t0 + tx];
    __syncthreads();
    #pragma unroll
    for (int i = ty; i < 32; i += 8)
        g_resid[((size_t)b * T_ + t0 + i) * D_ + d0 + tx] = tile[tx][i];
}

// ---------------------------------------------------------------------------
// fused distance + argmin: block = 128 rows x 1024 bins (128-bin chunks)
// dist(n,j) = ||c_j||^2 - 2 * r_n . c_j   (row-constant ||r||^2 dropped)
// Warp tile 32x64 (lane grid 4x8), 8x8 thread microtile, scalar FFMA.
__global__ __launch_bounds__(256, 2) void dist_argmin_kernel(
    const float* __restrict__ cb_all,  // [NQ][BINS][D]
    int q_layer)
{
    __shared__ union {
        struct { float A[16][132]; float B[16][132]; } g;
        struct { float v[128][17]; int idx[128][17]; } r;
    } sm;

    const float* cb    = cb_all + (size_t)q_layer * BINS_ * D_;
    const float* cnorm = g_cnorm + q_layer * BINS_;
    int*         codes = g_codes + q_layer * N_;

    const int tid = threadIdx.x;
    const int w   = tid >> 5;          // warp 0..7
    const int l   = tid & 31;
    const int wr  = w >> 1;            // warp row 0..3  (32 rows each)
    const int wc  = w & 1;             // warp col 0..1  (64 cols each)
    const int li  = l >> 3;            // lane row 0..3  (8 rows each)
    const int lj  = l & 7;             // lane col 0..7  (8 cols each)
    const int arow = wr * 32 + li * 8; // this thread's first row in tile
    const int bcol = wc * 64 + lj * 8; // this thread's first col in tile
    const int n0  = blockIdx.x * 128;

    const int lr = tid >> 2;           // 0..63 : row for global->smem loads
    const int lk = (tid & 3) << 2;     // 0,4,8,12 : k offset (float4)

    float bestv[8];
    int   besti[8];
    #pragma unroll
    for (int m = 0; m < 8; m++) { bestv[m] = CUDART_INF_F; besti[m] = 0; }

    for (int j0 = 0; j0 < BINS_; j0 += 128) {
        float acc[8][8];
        #pragma unroll
        for (int m = 0; m < 8; m++)
            #pragma unroll
            for (int n = 0; n < 8; n++) acc[m][n] = 0.0f;

        for (int k0 = 0; k0 < D_; k0 += 16) {
            #pragma unroll
            for (int it = 0; it < 2; it++) {
                int r = lr + it * 64;
                float4 av = *(const float4*)&g_resid[(size_t)(n0 + r) * D_ + k0 + lk];
                float4 bv = *(const float4*)&cb[(size_t)(j0 + r) * D_ + k0 + lk];
                sm.g.A[lk + 0][r] = av.x; sm.g.A[lk + 1][r] = av.y;
                sm.g.A[lk + 2][r] = av.z; sm.g.A[lk + 3][r] = av.w;
                sm.g.B[lk + 0][r] = bv.x; sm.g.B[lk + 1][r] = bv.y;
                sm.g.B[lk + 2][r] = bv.z; sm.g.B[lk + 3][r] = bv.w;
            }
            __syncthreads();
            #pragma unroll
            for (int k = 0; k < 16; k++) {
                float a[8], b[8];
                *(float4*)&a[0] = *(const float4*)&sm.g.A[k][arow];
                *(float4*)&a[4] = *(const float4*)&sm.g.A[k][arow + 4];
                *(float4*)&b[0] = *(const float4*)&sm.g.B[k][bcol];
                *(float4*)&b[4] = *(const float4*)&sm.g.B[k][bcol + 4];
                #pragma unroll
                for (int m = 0; m < 8; m++)
                    #pragma unroll
                    for (int n = 0; n < 8; n++)
                        acc[m][n] += a[m] * b[n];
            }
            __syncthreads();
        }

        // epilogue: distances + running argmin
        #pragma unroll
        for (int n = 0; n < 8; n++) {
            int   j  = j0 + bcol + n;
            float cn = __ldg(&cnorm[j]);
            #pragma unroll
            for (int m = 0; m < 8; m++) {
                float d = cn - 2.0f * acc[m][n];
                if (d < bestv[m] || (d == bestv[m] && j < besti[m])) {
                    bestv[m] = d;
                    besti[m] = j;
                }
            }
        }
    }

    // cross-thread reduce: row arow+m is held by 16 threads (wc x lj)
    __syncthreads();
    #pragma unroll
    for (int m = 0; m < 8; m++) {
        sm.r.v[arow + m][wc * 8 + lj]   = bestv[m];
        sm.r.idx[arow + m][wc * 8 + lj] = besti[m];
    }
    __syncthreads();
    if (tid < 128) {
        float bv = sm.r.v[tid][0];
        int   bi = sm.r.idx[tid][0];
        #pragma unroll
        for (int xk = 1; xk < 16; xk++) {
            float v = sm.r.v[tid][xk];
            int   i = sm.r.idx[tid][xk];
            if (v < bv || (v == bv && i < bi)) { bv = v; bi = i; }
        }
        codes[n0 + tid] = bi;
    }
}

// ---------------------------------------------------------------------------
// update: q = cb[idx]; loss += sum((r - q)^2); r -= q
__global__ __launch_bounds__(256) void update_kernel(
    const float* __restrict__ cb_all, int q_layer)
{
    __shared__ float warp_ss[8];
    const float* cb    = cb_all + (size_t)q_layer * BINS_ * D_;
    const int*   codes = g_codes + q_layer * N_;

    int warp = threadIdx.x >> 5;
    int lane = threadIdx.x & 31;
    int n    = blockIdx.x * 8 + warp;

    const float4* q4 = (const float4*)(cb + (size_t)codes[n] * D_);
    float4* r4 = (float4*)(g_resid + (size_t)n * D_);

    float ss = 0.0f;
    #pragma unroll
    for (int i = 0; i < 2; i++) {
        int e = lane + 32 * i;
        float4 r = r4[e];
        float4 q = q4[e];
        float dx = r.x - q.x, dy = r.y - q.y, dz = r.z - q.z, dw = r.w - q.w;
        ss += dx * dx + dy * dy + dz * dz + dw * dw;
        r4[e] = make_float4(dx, dy, dz, dw);
    }
    #pragma unroll
    for (int o = 16; o > 0; o >>= 1) ss += __shfl_xor_sync(0xFFFFFFFFu, ss, o);
    if (lane == 0) warp_ss[warp] = ss;
    __syncthreads();
    if (threadIdx.x == 0) {
        float s = 0.0f;
        #pragma unroll
        for (int w = 0; w < 8; w++) s += warp_ss[w];
        atomicAdd(&g_loss, s);
    }
}

// ---------------------------------------------------------------------------
// quantized = x - residual_final, transposed back to [B][D][T]
__global__ void finalize_out_kernel(const float* __restrict__ x,
                                    float* __restrict__ out)
{
    __shared__ float tile[32][33];
    int b  = blockIdx.z;
    int d0 = blockIdx.y * 32;
    int t0 = blockIdx.x * 32;
    int tx = threadIdx.x;
    int ty = threadIdx.y;
    #pragma unroll
    for (int i = ty; i < 32; i += 8)
        tile[i][tx] = g_resid[((size_t)b * T_ + t0 + i) * D_ + d0 + tx];
    __syncthreads();
    #pragma unroll
    for (int i = ty; i < 32; i += 8) {
        size_t xi = (size_t)b * D_ * T_ + (size_t)(d0 + i) * T_ + t0 + tx;
        out[xi] = x[xi] - tile[tx][i];
    }
}

// ---------------------------------------------------------------------------
__global__ void codes_to_float_kernel(float* __restrict__ out) {
    int i = blockIdx.x * 256 + threadIdx.x;
    if (i < CODES_ELEMS) out[i] = (float)g_codes[i];
}

__global__ void loss_write_kernel(float* __restrict__ out) {
    out[0] = g_loss * (1.0f / ((float)NQ_ * (float)N_ * (float)D_));
}

// ---------------------------------------------------------------------------
extern "C" void kernel_launch(void* const* d_in, const int* in_sizes, int n_in,
                              void* d_out, int out_size)
{
    const float* x  = (const float*)d_in[0];   // [B, D, T]
    const float* cb = (const float*)d_in[1];   // [NQ, BINS, D]
    float* out = (float*)d_out;

    zero_loss_kernel<<<1, 1>>>();
    cnorm_kernel<<<(NQ_ * BINS_) / 8, 256>>>(cb);
    {
        dim3 grid(T_ / 32, D_ / 32, B_);
        dim3 blk(32, 8);
        transpose_in_kernel<<<grid, blk>>>(x);
    }
    for (int q = 0; q < NQ_; q++) {
        dist_argmin_kernel<<<N_ / 128, 256>>>(cb, q);
        update_kernel<<<N_ / 8, 256>>>(cb, q);
    }
    {
        dim3 grid(T_ / 32, D_ / 32, B_);
        dim3 blk(32, 8);
        finalize_out_kernel<<<grid, blk>>>(x, out);
    }
    codes_to_float_kernel<<<(CODES_ELEMS + 255) / 256, 256>>>(out + QUANT_ELEMS);
    loss_write_kernel<<<1, 1>>>(out + QUANT_ELEMS + CODES_ELEMS);
}